// round 14
// baseline (speedup 1.0000x reference)
#include <cuda_runtime.h>
#include <cuda_bf16.h>
#include <math.h>

#define B_SZ 4
#define S_LEN 2048
#define D_MODEL 2048
#define H_NUM 16
#define DH 128
#define D3 6144
#define NTOK (B_SZ * S_LEN)   // 8192

// -------- scratch (allocation-free rule: __device__ globals) --------
__device__ __nv_bfloat16 g_xn  [(size_t)NTOK * D_MODEL];     // 32 MB
__device__ __nv_bfloat16 g_qkv [(size_t)NTOK * D3];          // 100 MB
__device__ __nv_bfloat16 g_ctx [(size_t)NTOK * D_MODEL];     // 32 MB
__device__ __nv_bfloat16 g_win [(size_t)D_MODEL * D3];       // 24 MB
__device__ __nv_bfloat16 g_wout[(size_t)D_MODEL * D_MODEL];  // 8 MB

// ---------- helpers ----------
#define CP_ASYNC16(dst, src) \
    asm volatile("cp.async.cg.shared.global [%0], [%1], 16;" :: "r"(dst), "l"(src))
#define CP_COMMIT() asm volatile("cp.async.commit_group;")

#define LDM_X4(r0, r1, r2, r3, addr) \
    asm volatile("ldmatrix.sync.aligned.m8n8.x4.shared.b16 {%0,%1,%2,%3}, [%4];" \
        : "=r"(r0), "=r"(r1), "=r"(r2), "=r"(r3) : "r"(addr))
#define LDM_X4_T(r0, r1, r2, r3, addr) \
    asm volatile("ldmatrix.sync.aligned.m8n8.x4.trans.shared.b16 {%0,%1,%2,%3}, [%4];" \
        : "=r"(r0), "=r"(r1), "=r"(r2), "=r"(r3) : "r"(addr))

__device__ __forceinline__ void mma_bf16(float* c, const unsigned* a, const unsigned* b) {
    asm volatile(
        "mma.sync.aligned.m16n8k16.row.col.f32.bf16.bf16.f32 "
        "{%0,%1,%2,%3}, {%4,%5,%6,%7}, {%8,%9}, {%0,%1,%2,%3};"
        : "+f"(c[0]), "+f"(c[1]), "+f"(c[2]), "+f"(c[3])
        : "r"(a[0]), "r"(a[1]), "r"(a[2]), "r"(a[3]), "r"(b[0]), "r"(b[1]));
}

__device__ __forceinline__ unsigned pack_bf16x2(float lo, float hi) {
    unsigned r;
    asm("cvt.rn.bf16x2.f32 %0, %1, %2;" : "=r"(r) : "f"(hi), "f"(lo));
    return r;
}

// single MUFU.EX2 op (exp2f without fast-math lowers to a slow libdevice poly)
__device__ __forceinline__ float ex2(float x) {
    float r;
    asm("ex2.approx.ftz.f32 %0, %1;" : "=f"(r) : "f"(x));
    return r;
}

// ===================== weight fp32 -> bf16 =====================
__global__ __launch_bounds__(256) void wcvt_kernel(
    const float* __restrict__ in, __nv_bfloat16* __restrict__ out, int n)
{
    int i = (blockIdx.x * 256 + threadIdx.x) * 8;
    if (i >= n) return;
    float4 v0 = *(const float4*)(in + i);
    float4 v1 = *(const float4*)(in + i + 4);
    uint4 o;
    o.x = pack_bf16x2(v0.x, v0.y);
    o.y = pack_bf16x2(v0.z, v0.w);
    o.z = pack_bf16x2(v1.x, v1.y);
    o.w = pack_bf16x2(v1.z, v1.w);
    *(uint4*)(out + i) = o;
}

// ===================== LayerNorm (bf16 output) =====================
__global__ __launch_bounds__(256) void ln_kernel(
    const float* __restrict__ X, const float* __restrict__ w,
    const float* __restrict__ b, __nv_bfloat16* __restrict__ out)
{
    int row = blockIdx.x;
    int t = threadIdx.x;
    int lane = t & 31, wrp = t >> 5;
    const float* x = X + (size_t)row * D_MODEL;

    float4 v0 = *(const float4*)(x + t * 4);
    float4 v1 = *(const float4*)(x + 1024 + t * 4);

    float s  = v0.x + v0.y + v0.z + v0.w + v1.x + v1.y + v1.z + v1.w;
    float sq = v0.x*v0.x + v0.y*v0.y + v0.z*v0.z + v0.w*v0.w
             + v1.x*v1.x + v1.y*v1.y + v1.z*v1.z + v1.w*v1.w;

    #pragma unroll
    for (int off = 16; off; off >>= 1) {
        s  += __shfl_xor_sync(0xffffffffu, s,  off);
        sq += __shfl_xor_sync(0xffffffffu, sq, off);
    }
    __shared__ float sh_s[8], sh_q[8];
    if (lane == 0) { sh_s[wrp] = s; sh_q[wrp] = sq; }
    __syncthreads();
    float tot = 0.f, totq = 0.f;
    #pragma unroll
    for (int i = 0; i < 8; ++i) { tot += sh_s[i]; totq += sh_q[i]; }
    float mean = tot * (1.0f / D_MODEL);
    float var  = totq * (1.0f / D_MODEL) - mean * mean;
    float inv  = rsqrtf(var + 1e-5f);

    __nv_bfloat16* o = out + (size_t)row * D_MODEL;
    int c0 = t * 4, c1 = 1024 + t * 4;
    float4 w0 = *(const float4*)(w + c0), w1 = *(const float4*)(w + c1);
    float4 b0 = *(const float4*)(b + c0), b1 = *(const float4*)(b + c1);
    uint2 p0, p1;
    p0.x = pack_bf16x2((v0.x - mean) * inv * w0.x + b0.x,
                       (v0.y - mean) * inv * w0.y + b0.y);
    p0.y = pack_bf16x2((v0.z - mean) * inv * w0.z + b0.z,
                       (v0.w - mean) * inv * w0.w + b0.w);
    p1.x = pack_bf16x2((v1.x - mean) * inv * w1.x + b1.x,
                       (v1.y - mean) * inv * w1.y + b1.y);
    p1.y = pack_bf16x2((v1.z - mean) * inv * w1.z + b1.z,
                       (v1.w - mean) * inv * w1.w + b1.w);
    *(uint2*)(o + c0) = p0;
    *(uint2*)(o + c1) = p1;
}

// ========== BF16 GEMM: 128x128x32, 4 warps, warp tile 64x64, 4-stage ==========
#define GAST 40
#define GBST 136
#define GA_BYTES (128 * GAST * 2)       // 10240
#define GB_BYTES (32 * GBST * 2)        // 8704
#define GSTAGE (GA_BYTES + GB_BYTES)    // 18944
#define GEMM_SMEM (4 * GSTAGE)          // 75776

__device__ __forceinline__ void gemm_load_tile(
    const __nv_bfloat16* __restrict__ A, const __nv_bfloat16* __restrict__ B,
    int K, int N, int m0, int n0, int k0, unsigned stg, int tid)
{
    #pragma unroll
    for (int i = 0; i < 4; ++i) {
        int id = tid + i * 128;
        int r = id >> 2, c = id & 3;
        CP_ASYNC16(stg + (unsigned)(r * 80 + c * 16),
                   A + (size_t)(m0 + r) * K + k0 + c * 8);
    }
    #pragma unroll
    for (int i = 0; i < 4; ++i) {
        int id = tid + i * 128;
        int r = id >> 4, c = id & 15;
        CP_ASYNC16(stg + (unsigned)GA_BYTES + (unsigned)(r * 272 + c * 16),
                   B + (size_t)(k0 + r) * N + n0 + c * 8);
    }
}

__global__ __launch_bounds__(128) void gemm_bf16(
    const __nv_bfloat16* __restrict__ A, const __nv_bfloat16* __restrict__ B,
    const float* __restrict__ R, float* __restrict__ Cf,
    __nv_bfloat16* __restrict__ Cb, int M, int N, int K)
{
    extern __shared__ char smc[];
    unsigned sb = (unsigned)__cvta_generic_to_shared(smc);

    int tid = threadIdx.x;
    int wid = tid >> 5, lane = tid & 31;
    int g = lane >> 2, tig = lane & 3;
    int wm = wid & 1, wn = wid >> 1;
    int m0 = blockIdx.y * 128, n0 = blockIdx.x * 128;
    int am = wm * 64, bn = wn * 64;

    float acc[4][8][4];
    #pragma unroll
    for (int i = 0; i < 4; ++i)
        #pragma unroll
        for (int j = 0; j < 8; ++j)
            #pragma unroll
            for (int r = 0; r < 4; ++r) acc[i][j][r] = 0.f;

    const int NT = K / 32;
    gemm_load_tile(A, B, K, N, m0, n0, 0, sb, tid);
    CP_COMMIT();
    gemm_load_tile(A, B, K, N, m0, n0, 32, sb + GSTAGE, tid);
    CP_COMMIT();
    gemm_load_tile(A, B, K, N, m0, n0, 64, sb + 2 * GSTAGE, tid);
    CP_COMMIT();

    int lrow = lane & 15, lhi = lane >> 4;

    for (int kt = 0; kt < NT; ++kt) {
        if (kt <= NT - 3)      asm volatile("cp.async.wait_group 2;");
        else if (kt == NT - 2) asm volatile("cp.async.wait_group 1;");
        else                   asm volatile("cp.async.wait_group 0;");
        __syncthreads();

        if (kt + 3 < NT) {
            gemm_load_tile(A, B, K, N, m0, n0, (kt + 3) * 32,
                           sb + (unsigned)(((kt + 3) & 3) * GSTAGE), tid);
            CP_COMMIT();
        }

        unsigned sA = sb + (unsigned)((kt & 3) * GSTAGE);
        unsigned sB = sA + (unsigned)GA_BYTES;

        #pragma unroll
        for (int s = 0; s < 2; ++s) {
            int ksb = s * 32;
            unsigned a[4][4];
            #pragma unroll
            for (int i = 0; i < 4; ++i)
                LDM_X4(a[i][0], a[i][1], a[i][2], a[i][3],
                       sA + (unsigned)((am + i * 16 + lrow) * 80 + ksb + lhi * 16));
            unsigned bf[8][2];
            #pragma unroll
            for (int jp = 0; jp < 4; ++jp) {
                unsigned t0, t1, t2, t3;
                LDM_X4_T(t0, t1, t2, t3,
                         sB + (unsigned)((s * 16 + lrow) * 272 +
                                         (bn + jp * 16 + lhi * 8) * 2));
                bf[2 * jp][0] = t0; bf[2 * jp][1] = t1;
                bf[2 * jp + 1][0] = t2; bf[2 * jp + 1][1] = t3;
            }
            #pragma unroll
            for (int i = 0; i < 4; ++i)
                #pragma unroll
                for (int j = 0; j < 8; ++j)
                    mma_bf16(acc[i][j], a[i], bf[j]);
        }
    }

    #pragma unroll
    for (int i = 0; i < 4; ++i) {
        int row0 = m0 + am + i * 16 + g;
        #pragma unroll
        for (int j = 0; j < 8; ++j) {
            int col = n0 + bn + j * 8 + 2 * tig;
            size_t idx0 = (size_t)row0 * N + col;
            size_t idx1 = idx0 + (size_t)8 * N;
            if (Cb) {
                *(unsigned*)(Cb + idx0) = pack_bf16x2(acc[i][j][0], acc[i][j][1]);
                *(unsigned*)(Cb + idx1) = pack_bf16x2(acc[i][j][2], acc[i][j][3]);
            } else {
                float2 o0 = make_float2(acc[i][j][0], acc[i][j][1]);
                float2 o1 = make_float2(acc[i][j][2], acc[i][j][3]);
                float2 r0 = *(const float2*)(R + idx0);
                float2 r1 = *(const float2*)(R + idx1);
                o0.x += r0.x; o0.y += r0.y;
                o1.x += r1.x; o1.y += r1.y;
                *(float2*)(Cf + idx0) = o0;
                *(float2*)(Cf + idx1) = o1;
            }
        }
    }
}

// ===================== RoPE in place on bf16 qkv =====================
__global__ __launch_bounds__(256) void rope_kernel(__nv_bfloat16* __restrict__ qkv)
{
    int t = blockIdx.x * blockDim.x + threadIdx.x;
    int i = t & 31;
    int h = (t >> 5) & 15;
    int s = (t >> 9) & 2047;
    int b = t >> 20;
    if (b >= B_SZ) return;

    size_t base = ((size_t)(b * S_LEN + s)) * D3 + h * DH;
    double th = (double)s * pow(10000.0, -(double)i / 32.0);
    float c = (float)cos(th), sn = (float)sin(th);

    __nv_bfloat162* q = (__nv_bfloat162*)(qkv + base + 2 * i);
    float x1 = __bfloat162float(q->x), x2 = __bfloat162float(q->y);
    *q = __floats2bfloat162_rn(x1 * c - x2 * sn, x2 * c + x1 * sn);

    __nv_bfloat162* k = (__nv_bfloat162*)(qkv + base + D_MODEL + 2 * i);
    x1 = __bfloat162float(k->x); x2 = __bfloat162float(k->y);
    *k = __floats2bfloat162_rn(x1 * c - x2 * sn, x2 * c + x1 * sn);
}

// ===================== FA2 attention: BQ=64, BK=64, Dh=128, 4 warps ===========
// S/P register-resident; softmax via raw MUFU.EX2; rescale skipped when the
// warp's row maxima are unchanged (ballot-uniform branch).
#define FQ_B 0u
#define FK_B 17408u
#define FV_B 52224u
#define FKV_TILE 17408u
#define ATTN_SMEM 87040

__global__ __launch_bounds__(128) void attn_kernel(
    const __nv_bfloat16* __restrict__ qkv, __nv_bfloat16* __restrict__ ctx)
{
    extern __shared__ char smc[];
    unsigned sb = (unsigned)__cvta_generic_to_shared(smc);

    int qt = blockIdx.x, h = blockIdx.y, b = blockIdx.z;
    int tid = threadIdx.x;
    int wid = tid >> 5, lane = tid & 31;
    int g = lane >> 2, tig = lane & 3;
    int lrow = lane & 15, lhi = lane >> 4;
    int q0 = qt * 64;
    const float SC2 = 0.1275174265f;   // (1/sqrt(128)) * log2(e)

    // ---- prologue: Q (64x128), K(0), V(0) ----
    const __nv_bfloat16* qbase = qkv + ((size_t)(b * S_LEN + q0)) * D3 + h * DH;
    #pragma unroll
    for (int it = 0; it < 8; ++it) {
        int id = tid + it * 128;
        int r = id >> 4, c = id & 15;
        CP_ASYNC16(sb + FQ_B + (unsigned)(r * 272 + c * 16),
                   qbase + (size_t)r * D3 + c * 8);
    }
    {
        const __nv_bfloat16* kb = qkv + ((size_t)(b * S_LEN)) * D3 + D_MODEL + h * DH;
        const __nv_bfloat16* vb = kb + D_MODEL;
        #pragma unroll
        for (int it = 0; it < 8; ++it) {
            int id = tid + it * 128;
            int r = id >> 4, c = id & 15;
            CP_ASYNC16(sb + FK_B + (unsigned)(r * 272 + c * 16), kb + (size_t)r * D3 + c * 8);
            CP_ASYNC16(sb + FV_B + (unsigned)(r * 272 + c * 16), vb + (size_t)r * D3 + c * 8);
        }
    }
    CP_COMMIT();
    asm volatile("cp.async.wait_group 0;");
    __syncthreads();

    unsigned qa[8][4];
    #pragma unroll
    for (int s = 0; s < 8; ++s)
        LDM_X4(qa[s][0], qa[s][1], qa[s][2], qa[s][3],
               sb + FQ_B + (unsigned)((wid * 16 + lrow) * 272 + s * 32 + lhi * 16));

    float oacc[16][4];
    #pragma unroll
    for (int jn = 0; jn < 16; ++jn)
        #pragma unroll
        for (int r = 0; r < 4; ++r) oacc[jn][r] = 0.f;
    float m0 = -1e30f, m1 = -1e30f, l0 = 0.f, l1 = 0.f;

    const int NT = S_LEN / 64;
    for (int kt = 0; kt < NT; ++kt) {
        int buf = kt & 1;
        __syncthreads();
        if (kt + 1 < NT) {
            unsigned nb = (unsigned)((buf ^ 1) * FKV_TILE);
            const __nv_bfloat16* kb = qkv + ((size_t)(b * S_LEN + (kt + 1) * 64)) * D3
                                      + D_MODEL + h * DH;
            const __nv_bfloat16* vb = kb + D_MODEL;
            #pragma unroll
            for (int it = 0; it < 8; ++it) {
                int id = tid + it * 128;
                int r = id >> 4, c = id & 15;
                CP_ASYNC16(sb + FK_B + nb + (unsigned)(r * 272 + c * 16),
                           kb + (size_t)r * D3 + c * 8);
                CP_ASYNC16(sb + FV_B + nb + (unsigned)(r * 272 + c * 16),
                           vb + (size_t)r * D3 + c * 8);
            }
            CP_COMMIT();
            asm volatile("cp.async.wait_group 1;");
        } else {
            asm volatile("cp.async.wait_group 0;");
        }
        __syncthreads();

        // ---- S = Q K^T ----
        float sc[8][4];
        #pragma unroll
        for (int j = 0; j < 8; ++j)
            #pragma unroll
            for (int r = 0; r < 4; ++r) sc[j][r] = 0.f;
        {
            unsigned sK = sb + FK_B + (unsigned)(buf * FKV_TILE);
            #pragma unroll
            for (int sp = 0; sp < 4; ++sp) {
                #pragma unroll
                for (int j = 0; j < 8; ++j) {
                    unsigned t0, t1, t2, t3;
                    LDM_X4(t0, t1, t2, t3,
                           sK + (unsigned)((j * 8 + (lane & 7)) * 272 +
                                           sp * 64 + (lane >> 3) * 16));
                    unsigned b0[2] = { t0, t1 }, b1[2] = { t2, t3 };
                    mma_bf16(sc[j], qa[2 * sp], b0);
                    mma_bf16(sc[j], qa[2 * sp + 1], b1);
                }
            }
        }

        // ---- register softmax (MUFU.EX2), log2 domain ----
        float mx0 = -1e30f, mx1 = -1e30f;
        #pragma unroll
        for (int j = 0; j < 8; ++j) {
            sc[j][0] *= SC2; sc[j][1] *= SC2;
            sc[j][2] *= SC2; sc[j][3] *= SC2;
            mx0 = fmaxf(mx0, fmaxf(sc[j][0], sc[j][1]));
            mx1 = fmaxf(mx1, fmaxf(sc[j][2], sc[j][3]));
        }
        mx0 = fmaxf(mx0, __shfl_xor_sync(0xffffffffu, mx0, 1));
        mx0 = fmaxf(mx0, __shfl_xor_sync(0xffffffffu, mx0, 2));
        mx1 = fmaxf(mx1, __shfl_xor_sync(0xffffffffu, mx1, 1));
        mx1 = fmaxf(mx1, __shfl_xor_sync(0xffffffffu, mx1, 2));
        float mn0 = fmaxf(m0, mx0), mn1 = fmaxf(m1, mx1);

        float su0 = 0.f, su1 = 0.f;
        #pragma unroll
        for (int j = 0; j < 8; ++j) {
            sc[j][0] = ex2(sc[j][0] - mn0);
            sc[j][1] = ex2(sc[j][1] - mn0);
            sc[j][2] = ex2(sc[j][2] - mn1);
            sc[j][3] = ex2(sc[j][3] - mn1);
            su0 += sc[j][0] + sc[j][1];
            su1 += sc[j][2] + sc[j][3];
        }
        su0 += __shfl_xor_sync(0xffffffffu, su0, 1);
        su0 += __shfl_xor_sync(0xffffffffu, su0, 2);
        su1 += __shfl_xor_sync(0xffffffffu, su1, 1);
        su1 += __shfl_xor_sync(0xffffffffu, su1, 2);

        // warp-uniform rescale skip: only rescale when some row max moved
        bool moved = (mn0 > m0) || (mn1 > m1);
        if (__ballot_sync(0xffffffffu, moved)) {
            float corr0 = ex2(m0 - mn0), corr1 = ex2(m1 - mn1);
            l0 = l0 * corr0 + su0;
            l1 = l1 * corr1 + su1;
            #pragma unroll
            for (int jn = 0; jn < 16; ++jn) {
                oacc[jn][0] *= corr0; oacc[jn][1] *= corr0;
                oacc[jn][2] *= corr1; oacc[jn][3] *= corr1;
            }
        } else {
            l0 += su0;
            l1 += su1;
        }
        m0 = mn0; m1 = mn1;

        unsigned pk[4][4];
        #pragma unroll
        for (int s = 0; s < 4; ++s) {
            pk[s][0] = pack_bf16x2(sc[2 * s][0],     sc[2 * s][1]);
            pk[s][1] = pack_bf16x2(sc[2 * s][2],     sc[2 * s][3]);
            pk[s][2] = pack_bf16x2(sc[2 * s + 1][0], sc[2 * s + 1][1]);
            pk[s][3] = pack_bf16x2(sc[2 * s + 1][2], sc[2 * s + 1][3]);
        }

        // ---- O += P V ----
        {
            unsigned sV = sb + FV_B + (unsigned)(buf * FKV_TILE);
            #pragma unroll
            for (int jn = 0; jn < 16; ++jn) {
                unsigned t0, t1, t2, t3;
                LDM_X4_T(t0, t1, t2, t3, sV + (unsigned)(lane * 272 + jn * 16));
                unsigned b0[2] = { t0, t1 }, b1[2] = { t2, t3 };
                mma_bf16(oacc[jn], pk[0], b0);
                mma_bf16(oacc[jn], pk[1], b1);
                LDM_X4_T(t0, t1, t2, t3, sV + (unsigned)((32 + lane) * 272 + jn * 16));
                unsigned b2[2] = { t0, t1 }, b3[2] = { t2, t3 };
                mma_bf16(oacc[jn], pk[2], b2);
                mma_bf16(oacc[jn], pk[3], b3);
            }
        }
    }

    // ---- epilogue: O /= l, bf16 ----
    float inv0 = 1.0f / l0, inv1 = 1.0f / l1;
    int row = q0 + wid * 16 + g;
    #pragma unroll
    for (int jn = 0; jn < 16; ++jn) {
        int col = h * DH + jn * 8 + 2 * tig;
        size_t i0 = ((size_t)(b * S_LEN + row)) * D_MODEL + col;
        size_t i1 = i0 + (size_t)8 * D_MODEL;
        *(unsigned*)(ctx + i0) = pack_bf16x2(oacc[jn][0] * inv0, oacc[jn][1] * inv0);
        *(unsigned*)(ctx + i1) = pack_bf16x2(oacc[jn][2] * inv1, oacc[jn][3] * inv1);
    }
}

// ===================== launcher =====================
extern "C" void kernel_launch(void* const* d_in, const int* in_sizes, int n_in,
                              void* d_out, int out_size)
{
    const float* X     = (const float*)d_in[0];
    const float* ln_w  = (const float*)d_in[1];
    const float* ln_b  = (const float*)d_in[2];
    const float* W_in  = (const float*)d_in[3];
    const float* W_out = (const float*)d_in[4];
    float* out = (float*)d_out;

    __nv_bfloat16 *xn, *qkv, *ctx, *win, *wout;
    cudaGetSymbolAddress((void**)&xn,   g_xn);
    cudaGetSymbolAddress((void**)&qkv,  g_qkv);
    cudaGetSymbolAddress((void**)&ctx,  g_ctx);
    cudaGetSymbolAddress((void**)&win,  g_win);
    cudaGetSymbolAddress((void**)&wout, g_wout);

    {
        int n1 = D_MODEL * D3;
        int n2 = D_MODEL * D_MODEL;
        wcvt_kernel<<<n1 / 2048, 256>>>(W_in,  win,  n1);
        wcvt_kernel<<<n2 / 2048, 256>>>(W_out, wout, n2);
    }

    ln_kernel<<<NTOK, 256>>>(X, ln_w, ln_b, xn);

    cudaFuncSetAttribute(gemm_bf16, cudaFuncAttributeMaxDynamicSharedMemorySize, GEMM_SMEM);

    dim3 g1(D3 / 128, NTOK / 128);
    gemm_bf16<<<g1, 128, GEMM_SMEM>>>(xn, win, nullptr, nullptr, qkv, NTOK, D3, D_MODEL);

    rope_kernel<<<(B_SZ * S_LEN * H_NUM * 32) / 256, 256>>>(qkv);

    cudaFuncSetAttribute(attn_kernel, cudaFuncAttributeMaxDynamicSharedMemorySize, ATTN_SMEM);
    attn_kernel<<<dim3(S_LEN / 64, H_NUM, B_SZ), 128, ATTN_SMEM>>>(qkv, ctx);

    dim3 g2(D_MODEL / 128, NTOK / 128);
    gemm_bf16<<<g2, 128, GEMM_SMEM>>>(ctx, wout, X, out, nullptr, NTOK, D_MODEL, D_MODEL);
}

// round 16
// speedup vs baseline: 1.8203x; 1.8203x over previous
#include <cuda_runtime.h>
#include <cuda_bf16.h>
#include <math.h>

#define B_SZ 4
#define S_LEN 2048
#define D_MODEL 2048
#define H_NUM 16
#define DH 128
#define D3 6144
#define NTOK (B_SZ * S_LEN)   // 8192

// -------- scratch (allocation-free rule: __device__ globals) --------
__device__ __nv_bfloat16 g_xn  [(size_t)NTOK * D_MODEL];     // 32 MB
__device__ __nv_bfloat16 g_qkv [(size_t)NTOK * D3];          // 100 MB
__device__ __nv_bfloat16 g_ctx [(size_t)NTOK * D_MODEL];     // 32 MB
__device__ __nv_bfloat16 g_win [(size_t)D_MODEL * D3];       // 24 MB
__device__ __nv_bfloat16 g_wout[(size_t)D_MODEL * D_MODEL];  // 8 MB

// ---------- helpers ----------
#define CP_ASYNC16(dst, src) \
    asm volatile("cp.async.cg.shared.global [%0], [%1], 16;" :: "r"(dst), "l"(src))
#define CP_COMMIT() asm volatile("cp.async.commit_group;")

#define LDM_X4(r0, r1, r2, r3, addr) \
    asm volatile("ldmatrix.sync.aligned.m8n8.x4.shared.b16 {%0,%1,%2,%3}, [%4];" \
        : "=r"(r0), "=r"(r1), "=r"(r2), "=r"(r3) : "r"(addr))
#define LDM_X4_T(r0, r1, r2, r3, addr) \
    asm volatile("ldmatrix.sync.aligned.m8n8.x4.trans.shared.b16 {%0,%1,%2,%3}, [%4];" \
        : "=r"(r0), "=r"(r1), "=r"(r2), "=r"(r3) : "r"(addr))

__device__ __forceinline__ void mma_bf16(float* c, const unsigned* a, const unsigned* b) {
    asm volatile(
        "mma.sync.aligned.m16n8k16.row.col.f32.bf16.bf16.f32 "
        "{%0,%1,%2,%3}, {%4,%5,%6,%7}, {%8,%9}, {%0,%1,%2,%3};"
        : "+f"(c[0]), "+f"(c[1]), "+f"(c[2]), "+f"(c[3])
        : "r"(a[0]), "r"(a[1]), "r"(a[2]), "r"(a[3]), "r"(b[0]), "r"(b[1]));
}

__device__ __forceinline__ unsigned pack_bf16x2(float lo, float hi) {
    unsigned r;
    asm("cvt.rn.bf16x2.f32 %0, %1, %2;" : "=r"(r) : "f"(hi), "f"(lo));
    return r;
}

// ===================== weight fp32 -> bf16 =====================
__global__ __launch_bounds__(256) void wcvt_kernel(
    const float* __restrict__ in, __nv_bfloat16* __restrict__ out, int n)
{
    int i = (blockIdx.x * 256 + threadIdx.x) * 8;
    if (i >= n) return;
    float4 v0 = *(const float4*)(in + i);
    float4 v1 = *(const float4*)(in + i + 4);
    uint4 o;
    o.x = pack_bf16x2(v0.x, v0.y);
    o.y = pack_bf16x2(v0.z, v0.w);
    o.z = pack_bf16x2(v1.x, v1.y);
    o.w = pack_bf16x2(v1.z, v1.w);
    *(uint4*)(out + i) = o;
}

// ===================== LayerNorm (bf16 output) =====================
__global__ __launch_bounds__(256) void ln_kernel(
    const float* __restrict__ X, const float* __restrict__ w,
    const float* __restrict__ b, __nv_bfloat16* __restrict__ out)
{
    int row = blockIdx.x;
    int t = threadIdx.x;
    int lane = t & 31, wrp = t >> 5;
    const float* x = X + (size_t)row * D_MODEL;

    float4 v0 = *(const float4*)(x + t * 4);
    float4 v1 = *(const float4*)(x + 1024 + t * 4);

    float s  = v0.x + v0.y + v0.z + v0.w + v1.x + v1.y + v1.z + v1.w;
    float sq = v0.x*v0.x + v0.y*v0.y + v0.z*v0.z + v0.w*v0.w
             + v1.x*v1.x + v1.y*v1.y + v1.z*v1.z + v1.w*v1.w;

    #pragma unroll
    for (int off = 16; off; off >>= 1) {
        s  += __shfl_xor_sync(0xffffffffu, s,  off);
        sq += __shfl_xor_sync(0xffffffffu, sq, off);
    }
    __shared__ float sh_s[8], sh_q[8];
    if (lane == 0) { sh_s[wrp] = s; sh_q[wrp] = sq; }
    __syncthreads();
    float tot = 0.f, totq = 0.f;
    #pragma unroll
    for (int i = 0; i < 8; ++i) { tot += sh_s[i]; totq += sh_q[i]; }
    float mean = tot * (1.0f / D_MODEL);
    float var  = totq * (1.0f / D_MODEL) - mean * mean;
    float inv  = rsqrtf(var + 1e-5f);

    __nv_bfloat16* o = out + (size_t)row * D_MODEL;
    int c0 = t * 4, c1 = 1024 + t * 4;
    float4 w0 = *(const float4*)(w + c0), w1 = *(const float4*)(w + c1);
    float4 b0 = *(const float4*)(b + c0), b1 = *(const float4*)(b + c1);
    uint2 p0, p1;
    p0.x = pack_bf16x2((v0.x - mean) * inv * w0.x + b0.x,
                       (v0.y - mean) * inv * w0.y + b0.y);
    p0.y = pack_bf16x2((v0.z - mean) * inv * w0.z + b0.z,
                       (v0.w - mean) * inv * w0.w + b0.w);
    p1.x = pack_bf16x2((v1.x - mean) * inv * w1.x + b1.x,
                       (v1.y - mean) * inv * w1.y + b1.y);
    p1.y = pack_bf16x2((v1.z - mean) * inv * w1.z + b1.z,
                       (v1.w - mean) * inv * w1.w + b1.w);
    *(uint2*)(o + c0) = p0;
    *(uint2*)(o + c1) = p1;
}

// ========== BF16 GEMM: 128x128x32, 4 warps, warp tile 64x64, 4-stage ==========
#define GAST 40
#define GBST 136
#define GA_BYTES (128 * GAST * 2)       // 10240
#define GB_BYTES (32 * GBST * 2)        // 8704
#define GSTAGE (GA_BYTES + GB_BYTES)    // 18944
#define GEMM_SMEM (4 * GSTAGE)          // 75776

__device__ __forceinline__ void gemm_load_tile(
    const __nv_bfloat16* __restrict__ A, const __nv_bfloat16* __restrict__ B,
    int K, int N, int m0, int n0, int k0, unsigned stg, int tid)
{
    #pragma unroll
    for (int i = 0; i < 4; ++i) {
        int id = tid + i * 128;
        int r = id >> 2, c = id & 3;
        CP_ASYNC16(stg + (unsigned)(r * 80 + c * 16),
                   A + (size_t)(m0 + r) * K + k0 + c * 8);
    }
    #pragma unroll
    for (int i = 0; i < 4; ++i) {
        int id = tid + i * 128;
        int r = id >> 4, c = id & 15;
        CP_ASYNC16(stg + (unsigned)GA_BYTES + (unsigned)(r * 272 + c * 16),
                   B + (size_t)(k0 + r) * N + n0 + c * 8);
    }
}

__global__ __launch_bounds__(128) void gemm_bf16(
    const __nv_bfloat16* __restrict__ A, const __nv_bfloat16* __restrict__ B,
    const float* __restrict__ R, float* __restrict__ Cf,
    __nv_bfloat16* __restrict__ Cb, int M, int N, int K)
{
    extern __shared__ char smc[];
    unsigned sb = (unsigned)__cvta_generic_to_shared(smc);

    int tid = threadIdx.x;
    int wid = tid >> 5, lane = tid & 31;
    int g = lane >> 2, tig = lane & 3;
    int wm = wid & 1, wn = wid >> 1;
    int m0 = blockIdx.y * 128, n0 = blockIdx.x * 128;
    int am = wm * 64, bn = wn * 64;

    float acc[4][8][4];
    #pragma unroll
    for (int i = 0; i < 4; ++i)
        #pragma unroll
        for (int j = 0; j < 8; ++j)
            #pragma unroll
            for (int r = 0; r < 4; ++r) acc[i][j][r] = 0.f;

    const int NT = K / 32;
    gemm_load_tile(A, B, K, N, m0, n0, 0, sb, tid);
    CP_COMMIT();
    gemm_load_tile(A, B, K, N, m0, n0, 32, sb + GSTAGE, tid);
    CP_COMMIT();
    gemm_load_tile(A, B, K, N, m0, n0, 64, sb + 2 * GSTAGE, tid);
    CP_COMMIT();

    int lrow = lane & 15, lhi = lane >> 4;

    for (int kt = 0; kt < NT; ++kt) {
        if (kt <= NT - 3)      asm volatile("cp.async.wait_group 2;");
        else if (kt == NT - 2) asm volatile("cp.async.wait_group 1;");
        else                   asm volatile("cp.async.wait_group 0;");
        __syncthreads();

        if (kt + 3 < NT) {
            gemm_load_tile(A, B, K, N, m0, n0, (kt + 3) * 32,
                           sb + (unsigned)(((kt + 3) & 3) * GSTAGE), tid);
            CP_COMMIT();
        }

        unsigned sA = sb + (unsigned)((kt & 3) * GSTAGE);
        unsigned sB = sA + (unsigned)GA_BYTES;

        #pragma unroll
        for (int s = 0; s < 2; ++s) {
            int ksb = s * 32;
            unsigned a[4][4];
            #pragma unroll
            for (int i = 0; i < 4; ++i)
                LDM_X4(a[i][0], a[i][1], a[i][2], a[i][3],
                       sA + (unsigned)((am + i * 16 + lrow) * 80 + ksb + lhi * 16));
            unsigned bf[8][2];
            #pragma unroll
            for (int jp = 0; jp < 4; ++jp) {
                unsigned t0, t1, t2, t3;
                LDM_X4_T(t0, t1, t2, t3,
                         sB + (unsigned)((s * 16 + lrow) * 272 +
                                         (bn + jp * 16 + lhi * 8) * 2));
                bf[2 * jp][0] = t0; bf[2 * jp][1] = t1;
                bf[2 * jp + 1][0] = t2; bf[2 * jp + 1][1] = t3;
            }
            #pragma unroll
            for (int i = 0; i < 4; ++i)
                #pragma unroll
                for (int j = 0; j < 8; ++j)
                    mma_bf16(acc[i][j], a[i], bf[j]);
        }
    }

    #pragma unroll
    for (int i = 0; i < 4; ++i) {
        int row0 = m0 + am + i * 16 + g;
        #pragma unroll
        for (int j = 0; j < 8; ++j) {
            int col = n0 + bn + j * 8 + 2 * tig;
            size_t idx0 = (size_t)row0 * N + col;
            size_t idx1 = idx0 + (size_t)8 * N;
            if (Cb) {
                *(unsigned*)(Cb + idx0) = pack_bf16x2(acc[i][j][0], acc[i][j][1]);
                *(unsigned*)(Cb + idx1) = pack_bf16x2(acc[i][j][2], acc[i][j][3]);
            } else {
                float2 o0 = make_float2(acc[i][j][0], acc[i][j][1]);
                float2 o1 = make_float2(acc[i][j][2], acc[i][j][3]);
                float2 r0 = *(const float2*)(R + idx0);
                float2 r1 = *(const float2*)(R + idx1);
                o0.x += r0.x; o0.y += r0.y;
                o1.x += r1.x; o1.y += r1.y;
                *(float2*)(Cf + idx0) = o0;
                *(float2*)(Cf + idx1) = o1;
            }
        }
    }
}

// ===================== RoPE in place on bf16 qkv (all-fp32 math) ==============
// inv_freq = 10000^(-i/32) = exp2f(-i/32 * log2(10000)); angles + sincos in
// fp32 — matches the reference's fp32 trig and removes the fp64 pow/cos/sin
// software sequences (~100 fp64 ops/thread) the old kernel burned.
__global__ __launch_bounds__(256) void rope_kernel(__nv_bfloat16* __restrict__ qkv)
{
    int t = blockIdx.x * blockDim.x + threadIdx.x;
    int i = t & 31;
    int h = (t >> 5) & 15;
    int s = (t >> 9) & 2047;
    int b = t >> 20;
    if (b >= B_SZ) return;

    size_t base = ((size_t)(b * S_LEN + s)) * D3 + h * DH;
    const float LOG2_10000 = 13.287712379549449f;
    float inv_freq = exp2f(-(float)i * (LOG2_10000 / 32.0f));
    float ang = (float)s * inv_freq;
    float sn, c;
    sincosf(ang, &sn, &c);

    __nv_bfloat162* q = (__nv_bfloat162*)(qkv + base + 2 * i);
    float x1 = __bfloat162float(q->x), x2 = __bfloat162float(q->y);
    *q = __floats2bfloat162_rn(x1 * c - x2 * sn, x2 * c + x1 * sn);

    __nv_bfloat162* k = (__nv_bfloat162*)(qkv + base + D_MODEL + 2 * i);
    x1 = __bfloat162float(k->x); x2 = __bfloat162float(k->y);
    *k = __floats2bfloat162_rn(x1 * c - x2 * sn, x2 * c + x1 * sn);
}

// ===================== FA2 attention: BQ=64, BK=64, Dh=128, 4 warps ===========
// (R12 version — best measured.)
#define FQ_B 0u
#define FK_B 17408u
#define FV_B 52224u
#define FKV_TILE 17408u
#define ATTN_SMEM 87040

__global__ __launch_bounds__(128) void attn_kernel(
    const __nv_bfloat16* __restrict__ qkv, __nv_bfloat16* __restrict__ ctx)
{
    extern __shared__ char smc[];
    unsigned sb = (unsigned)__cvta_generic_to_shared(smc);

    int qt = blockIdx.x, h = blockIdx.y, b = blockIdx.z;
    int tid = threadIdx.x;
    int wid = tid >> 5, lane = tid & 31;
    int g = lane >> 2, tig = lane & 3;
    int lrow = lane & 15, lhi = lane >> 4;
    int q0 = qt * 64;
    const float SC2 = 0.1275174265f;   // (1/sqrt(128)) * log2(e)

    const __nv_bfloat16* qbase = qkv + ((size_t)(b * S_LEN + q0)) * D3 + h * DH;
    #pragma unroll
    for (int it = 0; it < 8; ++it) {
        int id = tid + it * 128;
        int r = id >> 4, c = id & 15;
        CP_ASYNC16(sb + FQ_B + (unsigned)(r * 272 + c * 16),
                   qbase + (size_t)r * D3 + c * 8);
    }
    {
        const __nv_bfloat16* kb = qkv + ((size_t)(b * S_LEN)) * D3 + D_MODEL + h * DH;
        const __nv_bfloat16* vb = kb + D_MODEL;
        #pragma unroll
        for (int it = 0; it < 8; ++it) {
            int id = tid + it * 128;
            int r = id >> 4, c = id & 15;
            CP_ASYNC16(sb + FK_B + (unsigned)(r * 272 + c * 16), kb + (size_t)r * D3 + c * 8);
            CP_ASYNC16(sb + FV_B + (unsigned)(r * 272 + c * 16), vb + (size_t)r * D3 + c * 8);
        }
    }
    CP_COMMIT();
    asm volatile("cp.async.wait_group 0;");
    __syncthreads();

    unsigned qa[8][4];
    #pragma unroll
    for (int s = 0; s < 8; ++s)
        LDM_X4(qa[s][0], qa[s][1], qa[s][2], qa[s][3],
               sb + FQ_B + (unsigned)((wid * 16 + lrow) * 272 + s * 32 + lhi * 16));

    float oacc[16][4];
    #pragma unroll
    for (int jn = 0; jn < 16; ++jn)
        #pragma unroll
        for (int r = 0; r < 4; ++r) oacc[jn][r] = 0.f;
    float m0 = -1e30f, m1 = -1e30f, l0 = 0.f, l1 = 0.f;

    const int NT = S_LEN / 64;
    for (int kt = 0; kt < NT; ++kt) {
        int buf = kt & 1;
        __syncthreads();
        if (kt + 1 < NT) {
            unsigned nb = (unsigned)((buf ^ 1) * FKV_TILE);
            const __nv_bfloat16* kb = qkv + ((size_t)(b * S_LEN + (kt + 1) * 64)) * D3
                                      + D_MODEL + h * DH;
            const __nv_bfloat16* vb = kb + D_MODEL;
            #pragma unroll
            for (int it = 0; it < 8; ++it) {
                int id = tid + it * 128;
                int r = id >> 4, c = id & 15;
                CP_ASYNC16(sb + FK_B + nb + (unsigned)(r * 272 + c * 16),
                           kb + (size_t)r * D3 + c * 8);
                CP_ASYNC16(sb + FV_B + nb + (unsigned)(r * 272 + c * 16),
                           vb + (size_t)r * D3 + c * 8);
            }
            CP_COMMIT();
            asm volatile("cp.async.wait_group 1;");
        } else {
            asm volatile("cp.async.wait_group 0;");
        }
        __syncthreads();

        float sc[8][4];
        #pragma unroll
        for (int j = 0; j < 8; ++j)
            #pragma unroll
            for (int r = 0; r < 4; ++r) sc[j][r] = 0.f;
        {
            unsigned sK = sb + FK_B + (unsigned)(buf * FKV_TILE);
            #pragma unroll
            for (int sp = 0; sp < 4; ++sp) {
                #pragma unroll
                for (int j = 0; j < 8; ++j) {
                    unsigned t0, t1, t2, t3;
                    LDM_X4(t0, t1, t2, t3,
                           sK + (unsigned)((j * 8 + (lane & 7)) * 272 +
                                           sp * 64 + (lane >> 3) * 16));
                    unsigned b0[2] = { t0, t1 }, b1[2] = { t2, t3 };
                    mma_bf16(sc[j], qa[2 * sp], b0);
                    mma_bf16(sc[j], qa[2 * sp + 1], b1);
                }
            }
        }

        float mx0 = -1e30f, mx1 = -1e30f;
        #pragma unroll
        for (int j = 0; j < 8; ++j) {
            sc[j][0] *= SC2; sc[j][1] *= SC2;
            sc[j][2] *= SC2; sc[j][3] *= SC2;
            mx0 = fmaxf(mx0, fmaxf(sc[j][0], sc[j][1]));
            mx1 = fmaxf(mx1, fmaxf(sc[j][2], sc[j][3]));
        }
        mx0 = fmaxf(mx0, __shfl_xor_sync(0xffffffffu, mx0, 1));
        mx0 = fmaxf(mx0, __shfl_xor_sync(0xffffffffu, mx0, 2));
        mx1 = fmaxf(mx1, __shfl_xor_sync(0xffffffffu, mx1, 1));
        mx1 = fmaxf(mx1, __shfl_xor_sync(0xffffffffu, mx1, 2));
        float mn0 = fmaxf(m0, mx0), mn1 = fmaxf(m1, mx1);
        float corr0 = exp2f(m0 - mn0), corr1 = exp2f(m1 - mn1);
        float su0 = 0.f, su1 = 0.f;
        #pragma unroll
        for (int j = 0; j < 8; ++j) {
            sc[j][0] = exp2f(sc[j][0] - mn0);
            sc[j][1] = exp2f(sc[j][1] - mn0);
            sc[j][2] = exp2f(sc[j][2] - mn1);
            sc[j][3] = exp2f(sc[j][3] - mn1);
            su0 += sc[j][0] + sc[j][1];
            su1 += sc[j][2] + sc[j][3];
        }
        su0 += __shfl_xor_sync(0xffffffffu, su0, 1);
        su0 += __shfl_xor_sync(0xffffffffu, su0, 2);
        su1 += __shfl_xor_sync(0xffffffffu, su1, 1);
        su1 += __shfl_xor_sync(0xffffffffu, su1, 2);
        l0 = l0 * corr0 + su0;
        l1 = l1 * corr1 + su1;
        m0 = mn0; m1 = mn1;

        unsigned pk[4][4];
        #pragma unroll
        for (int s = 0; s < 4; ++s) {
            pk[s][0] = pack_bf16x2(sc[2 * s][0],     sc[2 * s][1]);
            pk[s][1] = pack_bf16x2(sc[2 * s][2],     sc[2 * s][3]);
            pk[s][2] = pack_bf16x2(sc[2 * s + 1][0], sc[2 * s + 1][1]);
            pk[s][3] = pack_bf16x2(sc[2 * s + 1][2], sc[2 * s + 1][3]);
        }

        #pragma unroll
        for (int jn = 0; jn < 16; ++jn) {
            oacc[jn][0] *= corr0; oacc[jn][1] *= corr0;
            oacc[jn][2] *= corr1; oacc[jn][3] *= corr1;
        }
        {
            unsigned sV = sb + FV_B + (unsigned)(buf * FKV_TILE);
            #pragma unroll
            for (int jn = 0; jn < 16; ++jn) {
                unsigned t0, t1, t2, t3;
                LDM_X4_T(t0, t1, t2, t3, sV + (unsigned)(lane * 272 + jn * 16));
                unsigned b0[2] = { t0, t1 }, b1[2] = { t2, t3 };
                mma_bf16(oacc[jn], pk[0], b0);
                mma_bf16(oacc[jn], pk[1], b1);
                LDM_X4_T(t0, t1, t2, t3, sV + (unsigned)((32 + lane) * 272 + jn * 16));
                unsigned b2[2] = { t0, t1 }, b3[2] = { t2, t3 };
                mma_bf16(oacc[jn], pk[2], b2);
                mma_bf16(oacc[jn], pk[3], b3);
            }
        }
    }

    float inv0 = 1.0f / l0, inv1 = 1.0f / l1;
    int row = q0 + wid * 16 + g;
    #pragma unroll
    for (int jn = 0; jn < 16; ++jn) {
        int col = h * DH + jn * 8 + 2 * tig;
        size_t i0 = ((size_t)(b * S_LEN + row)) * D_MODEL + col;
        size_t i1 = i0 + (size_t)8 * D_MODEL;
        *(unsigned*)(ctx + i0) = pack_bf16x2(oacc[jn][0] * inv0, oacc[jn][1] * inv0);
        *(unsigned*)(ctx + i1) = pack_bf16x2(oacc[jn][2] * inv1, oacc[jn][3] * inv1);
    }
}

// ===================== launcher =====================
extern "C" void kernel_launch(void* const* d_in, const int* in_sizes, int n_in,
                              void* d_out, int out_size)
{
    const float* X     = (const float*)d_in[0];
    const float* ln_w  = (const float*)d_in[1];
    const float* ln_b  = (const float*)d_in[2];
    const float* W_in  = (const float*)d_in[3];
    const float* W_out = (const float*)d_in[4];
    float* out = (float*)d_out;

    __nv_bfloat16 *xn, *qkv, *ctx, *win, *wout;
    cudaGetSymbolAddress((void**)&xn,   g_xn);
    cudaGetSymbolAddress((void**)&qkv,  g_qkv);
    cudaGetSymbolAddress((void**)&ctx,  g_ctx);
    cudaGetSymbolAddress((void**)&win,  g_win);
    cudaGetSymbolAddress((void**)&wout, g_wout);

    {
        int n1 = D_MODEL * D3;
        int n2 = D_MODEL * D_MODEL;
        wcvt_kernel<<<n1 / 2048, 256>>>(W_in,  win,  n1);
        wcvt_kernel<<<n2 / 2048, 256>>>(W_out, wout, n2);
    }

    ln_kernel<<<NTOK, 256>>>(X, ln_w, ln_b, xn);

    cudaFuncSetAttribute(gemm_bf16, cudaFuncAttributeMaxDynamicSharedMemorySize, GEMM_SMEM);

    dim3 g1(D3 / 128, NTOK / 128);
    gemm_bf16<<<g1, 128, GEMM_SMEM>>>(xn, win, nullptr, nullptr, qkv, NTOK, D3, D_MODEL);

    rope_kernel<<<(B_SZ * S_LEN * H_NUM * 32) / 256, 256>>>(qkv);

    cudaFuncSetAttribute(attn_kernel, cudaFuncAttributeMaxDynamicSharedMemorySize, ATTN_SMEM);
    attn_kernel<<<dim3(S_LEN / 64, H_NUM, B_SZ), 128, ATTN_SMEM>>>(qkv, ctx);

    dim3 g2(D_MODEL / 128, NTOK / 128);
    gemm_bf16<<<g2, 128, GEMM_SMEM>>>(ctx, wout, X, out, nullptr, NTOK, D_MODEL, D_MODEL);
}